// round 13
// baseline (speedup 1.0000x reference)
#include <cuda_runtime.h>

// YoloLayer2: x (16, 3*85, 76, 76) f32 -> out (16, 3, 76, 76, 85) f32
// FINAL (converged, R11): per-(b,a) transpose [85 x 5776] -> [5776 x 85]
// with YOLO head activations.
//  - TILE_P=64 pixels/block, 256 threads, 21.76 KB smem (~85% occupancy)
//  - warp-shaped item map (4 attrs x 8 quads/warp) -> conflict-free
//    transposed STS: bank (20m + attr) mod 32 hits all 32 banks
//  - evict-first (.cs) loads (input dead after one read), default cached
//    stores (L2 absorbs the write burst) -- measured optimal vs both
//    alternatives
//  - sigmoid via single-MUFU tanh.approx: 0.5*tanh(v/2)+0.5
// Measured: 32.1 us ncu / 39.4-39.6 us wall. Combined R+W traffic
// 188.5 MB / 32.1 us = 5.87 TB/s mixed = practical memory floor; four
// independent kernel structures all plateau here.

#define NUM_B 16
#define NUM_A 3
#define DIM_H 76
#define DIM_W 76
#define HW (DIM_H * DIM_W)        // 5776
#define ATTR 85
#define TILE_P 64                 // pixels per block (smem = 64*85*4 = 21760 B)
#define NTHREADS 256
#define NWARPS (NTHREADS / 32)
#define WITERS 44                 // 22 attr-groups (of 4, padded to 88) * 2 m-halves

// sigmoid(v) = 0.5*tanh(v/2) + 0.5  -- single MUFU (tanh.approx) + FMA
__device__ __forceinline__ float fsigmoid(float v) {
    float t;
    asm("tanh.approx.f32 %0, %1;" : "=f"(t) : "f"(v * 0.5f));
    return fmaf(t, 0.5f, 0.5f);
}

// streaming load: input is dead after one read -> evict-first keeps L2
// capacity for the write stream (which benefits from caching)
__device__ __forceinline__ float4 ldcs4(const float* p) {
    float4 r;
    asm("ld.global.cs.v4.f32 {%0,%1,%2,%3}, [%4];"
        : "=f"(r.x), "=f"(r.y), "=f"(r.z), "=f"(r.w) : "l"(p));
    return r;
}

__global__ __launch_bounds__(NTHREADS)
void yolo_kernel(const float* __restrict__ x, float* __restrict__ out) {
    __shared__ float sm[TILE_P * ATTR];   // 21760 bytes

    const int tile = blockIdx.x;          // pixel tile within (b,a)
    const int ba   = blockIdx.y;          // b*3 + a, 0..47
    const int a    = ba % NUM_A;

    // anchor_w = masked[0:3] = {10,13,16}; anchor_h = masked[1:4] = {13,16,30}
    const float AW[3] = {10.0f, 13.0f, 16.0f};
    const float AH[3] = {13.0f, 16.0f, 30.0f};
    const float sw = AW[a] * (1.0f / 608.0f);
    const float sh = AH[a] * (1.0f / 608.0f);

    const int p0     = tile * TILE_P;
    const int nvalid = min(TILE_P, HW - p0);   // 64, or 16 on the last tile
    const int tid    = threadIdx.x;
    const int warp   = tid >> 5;
    const int lane   = tid & 31;

    const int attr_lo = lane >> 3;        // 0..3 within attr-group
    const int m_lo    = lane & 7;         // 0..7 within m-half

    const float* __restrict__ base_in = x + (size_t)ba * ATTR * HW + p0;

    // Warp-iteration wi: attr = 4*(wi>>1) + attr_lo, m = 8*(wi&1) + m_lo.
    // STS banks: (20m + attr) mod 32 -> all 32 distinct -> conflict-free.
    for (int wi = warp; wi < WITERS; wi += NWARPS) {
        const int attr = ((wi >> 1) << 2) + attr_lo;   // 0..87 (88 virtual)
        const int m    = ((wi & 1) << 3) + m_lo;       // 0..15
        const int pl   = m << 2;                       // 0..60
        if (attr >= ATTR || pl >= nvalid) continue;

        float4 v = ldcs4(base_in + attr * HW + pl);
        float vv[4] = {v.x, v.y, v.z, v.w};
        float r[4];

        if (attr >= 4) {
            #pragma unroll
            for (int k = 0; k < 4; k++) r[k] = fsigmoid(vv[k]);
        } else if (attr == 0) {
            #pragma unroll
            for (int k = 0; k < 4; k++) {
                const int p   = p0 + pl + k;
                const int wi2 = p % DIM_W;
                r[k] = ((float)wi2 + fsigmoid(vv[k])) * (1.0f / 76.0f);
            }
        } else if (attr == 1) {
            #pragma unroll
            for (int k = 0; k < 4; k++) {
                const int p  = p0 + pl + k;
                const int hj = p / DIM_W;
                r[k] = ((float)hj + fsigmoid(vv[k])) * (1.0f / 76.0f);
            }
        } else if (attr == 2) {
            #pragma unroll
            for (int k = 0; k < 4; k++) r[k] = __expf(vv[k]) * sw;
        } else { // attr == 3
            #pragma unroll
            for (int k = 0; k < 4; k++) r[k] = __expf(vv[k]) * sh;
        }

        // Transposed smem store, conflict-free by construction
        float* __restrict__ row = sm + pl * ATTR + attr;
        #pragma unroll
        for (int k = 0; k < 4; k++) row[k * ATTR] = r[k];
    }
    __syncthreads();

    // Coalesced flat write of nvalid*85 contiguous floats (multiple of 4).
    // Default cache policy: L2 write caching absorbs the store burst.
    float* __restrict__ base_out = out + (size_t)(ba * HW + p0) * ATTR;
    const int total4 = (nvalid * ATTR) >> 2;
    const float4* __restrict__ s4 = (const float4*)sm;
    float4* __restrict__ o4 = (float4*)base_out;
    for (int k = tid; k < total4; k += NTHREADS) {
        o4[k] = s4[k];
    }
}

extern "C" void kernel_launch(void* const* d_in, const int* in_sizes, int n_in,
                              void* d_out, int out_size) {
    const float* x = (const float*)d_in[0];
    float* out = (float*)d_out;
    dim3 grid((HW + TILE_P - 1) / TILE_P, NUM_B * NUM_A);  // (91, 48)
    yolo_kernel<<<grid, NTHREADS>>>(x, out);
}

// round 14
// speedup vs baseline: 1.2135x; 1.2135x over previous
#include <cuda_runtime.h>

// YoloLayer2: x (16, 3*85, 76, 76) f32 -> out (16, 3, 76, 76, 85) f32
// R11 converged structure + explicit two-phase load batching:
// all 6 float4 LDGs issued back-to-back (MLP_eff = 6 guaranteed) before
// any compute/STS. Conflict-free warp-shaped STS, .cs loads, cached stores.

#define NUM_B 16
#define NUM_A 3
#define DIM_H 76
#define DIM_W 76
#define HW (DIM_H * DIM_W)        // 5776
#define ATTR 85
#define TILE_P 64                 // pixels per block (smem = 64*85*4 = 21760 B)
#define NTHREADS 256
#define NWARPS (NTHREADS / 32)
#define WITERS 44                 // 22 attr-groups (of 4, padded to 88) * 2 m-halves
#define MAXIT 6                   // ceil(WITERS / NWARPS)

// sigmoid(v) = 0.5*tanh(v/2) + 0.5  -- single MUFU (tanh.approx) + FMA
__device__ __forceinline__ float fsigmoid(float v) {
    float t;
    asm("tanh.approx.f32 %0, %1;" : "=f"(t) : "f"(v * 0.5f));
    return fmaf(t, 0.5f, 0.5f);
}

// streaming load: input is dead after one read
__device__ __forceinline__ float4 ldcs4(const float* p) {
    float4 r;
    asm("ld.global.cs.v4.f32 {%0,%1,%2,%3}, [%4];"
        : "=f"(r.x), "=f"(r.y), "=f"(r.z), "=f"(r.w) : "l"(p));
    return r;
}

__global__ __launch_bounds__(NTHREADS, 6)
void yolo_kernel(const float* __restrict__ x, float* __restrict__ out) {
    __shared__ float sm[TILE_P * ATTR];   // 21760 bytes

    const int tile = blockIdx.x;          // pixel tile within (b,a)
    const int ba   = blockIdx.y;          // b*3 + a, 0..47
    const int a    = ba % NUM_A;

    // anchor_w = masked[0:3] = {10,13,16}; anchor_h = masked[1:4] = {13,16,30}
    const float AW[3] = {10.0f, 13.0f, 16.0f};
    const float AH[3] = {13.0f, 16.0f, 30.0f};
    const float sw = AW[a] * (1.0f / 608.0f);
    const float sh = AH[a] * (1.0f / 608.0f);

    const int p0     = tile * TILE_P;
    const int nvalid = min(TILE_P, HW - p0);   // 64, or 16 on the last tile
    const int tid    = threadIdx.x;
    const int warp   = tid >> 5;
    const int lane   = tid & 31;

    const int attr_lo = lane >> 3;        // 0..3 within attr-group
    const int m_lo    = lane & 7;         // 0..7 within m-half

    const float* __restrict__ base_in = x + (size_t)ba * ATTR * HW + p0;

    // Item i -> wi = warp + i*NWARPS; attr = 4*(wi>>1)+attr_lo, m = 8*(wi&1)+m_lo.
    int  attr_v[MAXIT], pl_v[MAXIT];
    bool ok[MAXIT];
    #pragma unroll
    for (int i = 0; i < MAXIT; i++) {
        const int wi = warp + i * NWARPS;
        attr_v[i] = ((wi >> 1) << 2) + attr_lo;   // 0..87 (88 virtual)
        pl_v[i]   = (((wi & 1) << 3) + m_lo) << 2;
        ok[i] = (wi < WITERS) && (attr_v[i] < ATTR) && (pl_v[i] < nvalid);
    }

    // ---- phase 1: batch all loads (MLP = 6) ----
    float4 v[MAXIT];
    #pragma unroll
    for (int i = 0; i < MAXIT; i++)
        if (ok[i]) v[i] = ldcs4(base_in + attr_v[i] * HW + pl_v[i]);

    // ---- phase 2: compute + conflict-free transposed STS ----
    #pragma unroll
    for (int i = 0; i < MAXIT; i++) {
        if (!ok[i]) continue;
        const int attr = attr_v[i];
        const int pl   = pl_v[i];
        float vv[4] = {v[i].x, v[i].y, v[i].z, v[i].w};
        float r[4];

        if (attr >= 4) {
            #pragma unroll
            for (int k = 0; k < 4; k++) r[k] = fsigmoid(vv[k]);
        } else if (attr == 0) {
            #pragma unroll
            for (int k = 0; k < 4; k++) {
                const int p   = p0 + pl + k;
                const int wi2 = p % DIM_W;
                r[k] = ((float)wi2 + fsigmoid(vv[k])) * (1.0f / 76.0f);
            }
        } else if (attr == 1) {
            #pragma unroll
            for (int k = 0; k < 4; k++) {
                const int p  = p0 + pl + k;
                const int hj = p / DIM_W;
                r[k] = ((float)hj + fsigmoid(vv[k])) * (1.0f / 76.0f);
            }
        } else if (attr == 2) {
            #pragma unroll
            for (int k = 0; k < 4; k++) r[k] = __expf(vv[k]) * sw;
        } else { // attr == 3
            #pragma unroll
            for (int k = 0; k < 4; k++) r[k] = __expf(vv[k]) * sh;
        }

        // STS banks: (20m + attr) mod 32 -> all 32 distinct -> conflict-free
        float* __restrict__ row = sm + pl * ATTR + attr;
        #pragma unroll
        for (int k = 0; k < 4; k++) row[k * ATTR] = r[k];
    }
    __syncthreads();

    // Coalesced flat write of nvalid*85 contiguous floats (multiple of 4).
    // Default cache policy: L2 write caching absorbs the store burst.
    float* __restrict__ base_out = out + (size_t)(ba * HW + p0) * ATTR;
    const int total4 = (nvalid * ATTR) >> 2;
    const float4* __restrict__ s4 = (const float4*)sm;
    float4* __restrict__ o4 = (float4*)base_out;
    for (int k = tid; k < total4; k += NTHREADS) {
        o4[k] = s4[k];
    }
}

extern "C" void kernel_launch(void* const* d_in, const int* in_sizes, int n_in,
                              void* d_out, int out_size) {
    const float* x = (const float*)d_in[0];
    float* out = (float*)d_out;
    dim3 grid((HW + TILE_P - 1) / TILE_P, NUM_B * NUM_A);  // (91, 48)
    yolo_kernel<<<grid, NTHREADS>>>(x, out);
}